// round 16
// baseline (speedup 1.0000x reference)
#include <cuda_runtime.h>
#include <cuda_fp16.h>
#include <cstdint>

#define D_DIM 256
#define NTOK  65536
#define KCODE 4096
#define NT_HALF 16    // tiles per CTA (half of E)
#define NTILES (NTOK / 128)

// ---------------- scratch globals ----------------
__device__ float  g_esqp[KCODE];        // esq + 2048 (fp32)
__device__ int    g_counts[KCODE];
__device__ float  g_partials[NTILES];
__device__ __align__(16) __half g_Eh[KCODE * D_DIM];
__device__ __align__(16) __half g_Zh[NTOK * D_DIM];
__device__ __align__(16) uint32_t g_topk[NTOK * 8];
__device__ int    g_tile_done[NTILES];
__device__ int    g_done;

// SMEM: A 64KB | B0 64KB | B1 64KB | tops 4KB
#define SM_A    0
#define SM_B0   65536
#define SM_B1   131072
#define SM_TOP  196608
#define SMEM_TOTAL 200704

static __device__ __forceinline__ uint32_t smem_u32(const void* p) {
    uint32_t a;
    asm("{ .reg .u64 t; cvta.to.shared.u64 t, %1; cvt.u32.u64 %0, t; }" : "=r"(a) : "l"(p));
    return a;
}
static __device__ __forceinline__ void ldsm4(uint32_t* r, uint32_t addr) {
    asm volatile("ldmatrix.sync.aligned.m8n8.x4.shared.b16 {%0,%1,%2,%3}, [%4];"
                 : "=r"(r[0]), "=r"(r[1]), "=r"(r[2]), "=r"(r[3]) : "r"(addr));
}
static __device__ __forceinline__ void hmma16816_f16(uint32_t& c0, uint32_t& c1,
                                                     const uint32_t* a, uint32_t b0, uint32_t b1) {
    asm volatile("mma.sync.aligned.m16n8k16.row.col.f16.f16.f16.f16 "
                 "{%0,%1}, {%2,%3,%4,%5}, {%6,%7}, {%0,%1};"
                 : "+r"(c0), "+r"(c1)
                 : "r"(a[0]), "r"(a[1]), "r"(a[2]), "r"(a[3]), "r"(b0), "r"(b1));
}
static __device__ __forceinline__ void cpasync16(uint32_t sa, const void* ga) {
    asm volatile("cp.async.cg.shared.global [%0], [%1], 16;" :: "r"(sa), "l"(ga));
}
static __device__ __forceinline__ void ins4u(uint32_t k, uint32_t& t0, uint32_t& t1,
                                             uint32_t& t2, uint32_t& t3) {
    if (k < t3) {
        uint32_t m2 = min(t2, k);  t3 = max(t2, k);
        uint32_t m1 = min(t1, m2); t2 = max(t1, m2);
        uint32_t m0 = min(t0, m1); t1 = max(t0, m1); t0 = m0;
    }
}

// ---------------- kernel 1: fused prep (E + Z) ----------------
__global__ void prep_all_kernel(const float* __restrict__ E, const float* __restrict__ Z) {
    int warp = threadIdx.x >> 5, lane = threadIdx.x & 31;
    if (blockIdx.x < KCODE / 8) {
        int k = blockIdx.x * 8 + warp;
        const float* row = E + (size_t)k * D_DIM;
        float4 a = *reinterpret_cast<const float4*>(row + lane * 8);
        float4 b = *reinterpret_cast<const float4*>(row + lane * 8 + 4);
        float s = a.x * a.x + a.y * a.y + a.z * a.z + a.w * a.w
                + b.x * b.x + b.y * b.y + b.z * b.z + b.w * b.w;
#pragma unroll
        for (int o = 16; o > 0; o >>= 1) s += __shfl_xor_sync(0xffffffffu, s, o);
        __half h[8];
        h[0] = __float2half_rn(a.x); h[1] = __float2half_rn(a.y);
        h[2] = __float2half_rn(a.z); h[3] = __float2half_rn(a.w);
        h[4] = __float2half_rn(b.x); h[5] = __float2half_rn(b.y);
        h[6] = __float2half_rn(b.z); h[7] = __float2half_rn(b.w);
        *reinterpret_cast<uint4*>(g_Eh + (size_t)k * D_DIM + lane * 8) = *reinterpret_cast<uint4*>(h);
        if (lane == 0) g_esqp[k] = s + 2048.0f;
        if (blockIdx.x < 16) g_counts[blockIdx.x * 256 + threadIdx.x] = 0;
    } else {
        int n = (blockIdx.x - KCODE / 8) * 8 + warp;
        const float* row = Z + (size_t)n * D_DIM;
        float4 a = *reinterpret_cast<const float4*>(row + lane * 8);
        float4 b = *reinterpret_cast<const float4*>(row + lane * 8 + 4);
        __half h[8];
        h[0] = __float2half_rn(a.x); h[1] = __float2half_rn(a.y);
        h[2] = __float2half_rn(a.z); h[3] = __float2half_rn(a.w);
        h[4] = __float2half_rn(b.x); h[5] = __float2half_rn(b.y);
        h[6] = __float2half_rn(b.z); h[7] = __float2half_rn(b.w);
        *reinterpret_cast<uint4*>(g_Zh + (size_t)n * D_DIM + lane * 8) = *reinterpret_cast<uint4*>(h);
    }
}

// ---------------- kernel 2: N-split HMMA GEMM + top-4 + inline rescue ----------------
static __device__ __forceinline__ void load_tile_f16(uint32_t dst, const __half* gsrc, int tid) {
    const char* gbase = (const char*)gsrc;
#pragma unroll
    for (int i = 0; i < 16; i++) {
        int c = tid + i * 256;
        int row = c >> 5, ch = c & 31;
        uint32_t sa = dst + row * 512 + (uint32_t)((ch ^ (row & 7)) << 4);
        cpasync16(sa, gbase + row * 512 + ch * 16);
    }
}

static __device__ __forceinline__ void tile_body(
    int nt, bool hasPrev, int n0base, uint32_t sb, int tid, int lane, int wm, int wn,
    uint32_t cur[2][8][2], uint32_t prev[2][8][2], uint32_t T[4][4])
{
    if (nt < NT_HALF - 1) asm volatile("cp.async.wait_group 1;" ::: "memory");
    else                  asm volatile("cp.async.wait_group 0;" ::: "memory");
    __syncthreads();
    const uint32_t Bb = sb + ((nt & 1) ? SM_B1 : SM_B0);

    float2 e2[8];
    const int kbase = n0base + (nt - 1) * 128 + wn * 64 + (lane & 3) * 2;
    if (hasPrev) {
#pragma unroll
        for (int nj = 0; nj < 8; nj++)
            e2[nj] = *reinterpret_cast<const float2*>(g_esqp + kbase + nj * 8);
    }

#pragma unroll
    for (int mi = 0; mi < 2; mi++)
#pragma unroll
        for (int nj = 0; nj < 8; nj++) { cur[mi][nj][0] = 0u; cur[mi][nj][1] = 0u; }

#pragma unroll
    for (int ks = 0; ks < 16; ks++) {
        uint32_t a[2][4], b[4][4];
#pragma unroll
        for (int mi = 0; mi < 2; mi++) {
            int ar = wm * 32 + mi * 16 + (lane & 15);
            int ch = ks * 2 + (lane >> 4);
            ldsm4(a[mi], sb + SM_A + ar * 512 + ((ch ^ (ar & 7)) << 4));
        }
#pragma unroll
        for (int g = 0; g < 4; g++) {
            int br = wn * 64 + g * 16 + (lane & 7) + ((lane >> 4) & 1) * 8;
            int ch = ks * 2 + ((lane >> 3) & 1);
            ldsm4(b[g], Bb + br * 512 + ((ch ^ (br & 7)) << 4));
        }
#pragma unroll
        for (int mi = 0; mi < 2; mi++)
#pragma unroll
            for (int g = 0; g < 4; g++) {
                hmma16816_f16(cur[mi][2 * g][0],     cur[mi][2 * g][1],     a[mi], b[g][0], b[g][1]);
                hmma16816_f16(cur[mi][2 * g + 1][0], cur[mi][2 * g + 1][1], a[mi], b[g][2], b[g][3]);
            }

        if (hasPrev) {
            const int nj = ks >> 1;
            const int mi = ks & 1;
            const int kb = kbase + nj * 8;
#pragma unroll
            for (int h = 0; h < 2; h++) {
                const int s = mi * 2 + h;
                float2 d = __half22float2(*reinterpret_cast<__half2*>(&prev[mi][nj][h]));
                float v0 = fmaf(-2.0f, d.x, e2[nj].x);
                float v1 = fmaf(-2.0f, d.y, e2[nj].y);
                uint32_t k0 = (__float_as_uint(v0) & 0xFFFFF000u) | (uint32_t)kb;
                uint32_t k1 = (__float_as_uint(v1) & 0xFFFFF000u) | (uint32_t)(kb + 1);
                ins4u(k0, T[s][0], T[s][1], T[s][2], T[s][3]);
                ins4u(k1, T[s][0], T[s][1], T[s][2], T[s][3]);
            }
        }
    }
    __syncthreads();
    if (nt + 2 < NT_HALF) {
        load_tile_f16(sb + ((nt & 1) ? SM_B1 : SM_B0),
                      g_Eh + (size_t)(n0base + (nt + 2) * 128) * D_DIM, tid);
        asm volatile("cp.async.commit_group;" ::: "memory");
    }
}

static __device__ __forceinline__ void tail_epilogue(
    int n0base, int lane, int wn, uint32_t prev[2][8][2], uint32_t T[4][4])
{
    const int kbase = n0base + (NT_HALF - 1) * 128 + wn * 64 + (lane & 3) * 2;
#pragma unroll
    for (int nj = 0; nj < 8; nj++) {
        const int kb = kbase + nj * 8;
        float2 e2 = *reinterpret_cast<const float2*>(g_esqp + kb);
#pragma unroll
        for (int mi = 0; mi < 2; mi++)
#pragma unroll
            for (int h = 0; h < 2; h++) {
                const int s = mi * 2 + h;
                float2 d = __half22float2(*reinterpret_cast<__half2*>(&prev[mi][nj][h]));
                float v0 = fmaf(-2.0f, d.x, e2.x);
                float v1 = fmaf(-2.0f, d.y, e2.y);
                uint32_t k0 = (__float_as_uint(v0) & 0xFFFFF000u) | (uint32_t)kb;
                uint32_t k1 = (__float_as_uint(v1) & 0xFFFFF000u) | (uint32_t)(kb + 1);
                ins4u(k0, T[s][0], T[s][1], T[s][2], T[s][3]);
                ins4u(k1, T[s][0], T[s][1], T[s][2], T[s][3]);
            }
    }
}

__global__ __launch_bounds__(256, 1)
void approx_kernel(const float* __restrict__ Z, const float* __restrict__ E,
                   float* __restrict__ zq_out, float* __restrict__ out_idx_f,
                   float* __restrict__ out_scalars) {
    extern __shared__ char smem[];
    const uint32_t sb = smem_u32(smem);
    const int tid = threadIdx.x;
    const int lane = tid & 31;
    const int wid = tid >> 5;
    const int wm = wid & 3;
    const int wn = wid >> 2;
    const int tile = blockIdx.x >> 1;
    const int m0 = tile * 128;
    const int half = blockIdx.x & 1;
    const int n0base = half * (NT_HALF * 128);

    load_tile_f16(sb + SM_A, g_Zh + (size_t)m0 * D_DIM, tid);
    load_tile_f16(sb + SM_B0, g_Eh + (size_t)n0base * D_DIM, tid);
    asm volatile("cp.async.commit_group;" ::: "memory");
    load_tile_f16(sb + SM_B1, g_Eh + (size_t)(n0base + 128) * D_DIM, tid);
    asm volatile("cp.async.commit_group;" ::: "memory");

    uint32_t T[4][4];
#pragma unroll
    for (int s = 0; s < 4; s++) { T[s][0] = T[s][1] = T[s][2] = T[s][3] = 0xFFFFFFFFu; }

    uint32_t accA[2][8][2], accB[2][8][2];

#pragma unroll 1
    for (int p = 0; p < NT_HALF / 2; p++) {
        tile_body(2 * p,     (p > 0), n0base, sb, tid, lane, wm, wn, accA, accB, T);
        tile_body(2 * p + 1, true,    n0base, sb, tid, lane, wm, wn, accB, accA, T);
    }
    tail_epilogue(n0base, lane, wn, accB, T);

#pragma unroll
    for (int off = 1; off <= 2; off <<= 1) {
#pragma unroll
        for (int s = 0; s < 4; s++) {
            uint32_t o0 = __shfl_xor_sync(0xffffffffu, T[s][0], off);
            uint32_t o1 = __shfl_xor_sync(0xffffffffu, T[s][1], off);
            uint32_t o2 = __shfl_xor_sync(0xffffffffu, T[s][2], off);
            uint32_t o3 = __shfl_xor_sync(0xffffffffu, T[s][3], off);
            ins4u(o0, T[s][0], T[s][1], T[s][2], T[s][3]);
            ins4u(o1, T[s][0], T[s][1], T[s][2], T[s][3]);
            ins4u(o2, T[s][0], T[s][1], T[s][2], T[s][3]);
            ins4u(o3, T[s][0], T[s][1], T[s][2], T[s][3]);
        }
    }

    uint32_t* smk = reinterpret_cast<uint32_t*>(smem + SM_TOP);
    if ((lane & 3) == 0) {
#pragma unroll
        for (int s = 0; s < 4; s++) {
            int r = wm * 32 + (s >> 1) * 16 + (s & 1) * 8 + (lane >> 2);
            uint32_t* dst = smk + (r * 2 + wn) * 4;
            dst[0] = T[s][0]; dst[1] = T[s][1]; dst[2] = T[s][2]; dst[3] = T[s][3];
        }
    }
    __syncthreads();
    if (tid < 128) {
        uint4 A4 = *reinterpret_cast<uint4*>(smk + (tid * 2) * 4);
        uint4 B4 = *reinterpret_cast<uint4*>(smk + (tid * 2 + 1) * 4);
        uint32_t a0 = A4.x, a1 = A4.y, a2 = A4.z, a3 = A4.w;
        ins4u(B4.x, a0, a1, a2, a3);
        ins4u(B4.y, a0, a1, a2, a3);
        ins4u(B4.z, a0, a1, a2, a3);
        ins4u(B4.w, a0, a1, a2, a3);
        *reinterpret_cast<uint4*>(&g_topk[(size_t)(m0 + tid) * 8 + half * 4]) =
            make_uint4(a0, a1, a2, a3);
    }
    __syncthreads();

    // ---- tile ticket: second CTA of this tile performs the rescue ----
    __shared__ int do_rescue;
    if (tid == 0) {
        __threadfence();
        int old = atomicAdd(&g_tile_done[tile], 1);
        do_rescue = (old == 1);
    }
    __syncthreads();
    if (!do_rescue) return;
    __threadfence();   // acquire: see peer CTA's g_topk writes

    // ---- inline rescue: 8 warps x 16 tokens ----
    float s_acc = 0.f;
#pragma unroll 1
    for (int i = 0; i < 16; i++) {
        const int token = m0 + wid * 16 + i;
        const float* zr = Z + (size_t)token * D_DIM;
        float4 z0 = *reinterpret_cast<const float4*>(zr + lane * 8);
        float4 z1 = *reinterpret_cast<const float4*>(zr + lane * 8 + 4);

        uint4 tkA = *reinterpret_cast<const uint4*>(&g_topk[(size_t)token * 8]);
        uint4 tkB = *reinterpret_cast<const uint4*>(&g_topk[(size_t)token * 8 + 4]);
        uint32_t a0 = tkA.x, a1 = tkA.y, a2 = tkA.z, a3 = tkA.w;
        ins4u(tkB.x, a0, a1, a2, a3);
        ins4u(tkB.y, a0, a1, a2, a3);
        ins4u(tkB.z, a0, a1, a2, a3);
        ins4u(tkB.w, a0, a1, a2, a3);

        int ks[4] = { (int)(a0 & 4095u), (int)(a1 & 4095u), (int)(a2 & 4095u), (int)(a3 & 4095u) };
        float dots[4];
#pragma unroll
        for (int j = 0; j < 4; j++) {
            const float* er = E + (size_t)ks[j] * D_DIM;
            float4 e0 = *reinterpret_cast<const float4*>(er + lane * 8);
            float4 e1 = *reinterpret_cast<const float4*>(er + lane * 8 + 4);
            dots[j] = z0.x * e0.x + z0.y * e0.y + z0.z * e0.z + z0.w * e0.w
                    + z1.x * e1.x + z1.y * e1.y + z1.z * e1.z + z1.w * e1.w;
        }
#pragma unroll
        for (int o = 16; o > 0; o >>= 1)
#pragma unroll
            for (int j = 0; j < 4; j++) dots[j] += __shfl_xor_sync(0xffffffffu, dots[j], o);

        float bv = 3.4e38f; int bk = 0x7FFFFFFF;
#pragma unroll
        for (int j = 0; j < 4; j++) {
            float v = g_esqp[ks[j]] - 2048.0f - 2.0f * dots[j];
            if (v < bv || (v == bv && ks[j] < bk)) { bv = v; bk = ks[j]; }
        }

        const float* er = E + (size_t)bk * D_DIM;
        float* orow = zq_out + (size_t)token * D_DIM;
#pragma unroll
        for (int h = 0; h < 2; h++) {
            int off = h * 128 + lane * 4;
            float4 ev = *reinterpret_cast<const float4*>(er + off);
            float4 zv = *reinterpret_cast<const float4*>(zr + off);
            float dx = ev.x - zv.x, dy = ev.y - zv.y, dz = ev.z - zv.z, dw = ev.w - zv.w;
            s_acc += dx * dx + dy * dy + dz * dz + dw * dw;
            *reinterpret_cast<float4*>(orow + off) = ev;
        }
        if (lane == 0) {
            atomicAdd(&g_counts[bk], 1);
            out_idx_f[token] = (float)bk;
        }
    }
#pragma unroll
    for (int o = 16; o > 0; o >>= 1) s_acc += __shfl_down_sync(0xffffffffu, s_acc, o);
    __shared__ float sh[8];
    __shared__ int last;
    if (lane == 0) sh[wid] = s_acc;
    __syncthreads();
    if (tid == 0) {
        float t = 0.f;
        for (int w = 0; w < 8; w++) t += sh[w];
        g_partials[tile] = t;
        g_tile_done[tile] = 0;     // reset for next graph replay
        __threadfence();
        int ticket = atomicAdd(&g_done, 1);
        last = (ticket == NTILES - 1) ? 1 : 0;
    }
    __syncthreads();
    if (!last) return;

    // ---- finalize (last rescue CTA) ----
    __shared__ float red[256];
    float acc = 0.f;
    for (int i = tid; i < NTILES; i += 256) acc += g_partials[i];
    red[tid] = acc;
    __syncthreads();
    for (int st = 128; st > 0; st >>= 1) {
        if (tid < st) red[tid] += red[tid + st];
        __syncthreads();
    }
    float loss = 0.1f * red[0] / (float)((size_t)NTOK * D_DIM);
    __syncthreads();
    float e = 0.f;
    for (int i = tid; i < KCODE; i += 256) {
        float p = (float)g_counts[i] / (float)NTOK;
        e += p * logf(p + 1e-10f);
    }
    red[tid] = e;
    __syncthreads();
    for (int st = 128; st > 0; st >>= 1) {
        if (tid < st) red[tid] += red[tid + st];
        __syncthreads();
    }
    if (tid == 0) {
        out_scalars[0] = loss;
        out_scalars[1] = expf(-red[0]);
        g_done = 0;
    }
}

extern "C" void kernel_launch(void* const* d_in, const int* in_sizes, int n_in,
                              void* d_out, int out_size) {
    const float* Z = (const float*)d_in[0];
    const float* E = (const float*)d_in[1];
    int N = in_sizes[0] / D_DIM;
    int K = in_sizes[1] / D_DIM;

    float* out  = (float*)d_out;
    float* zq   = out;
    float* idxf = out + (size_t)N * D_DIM;
    float* scal = idxf + N;

    cudaFuncSetAttribute(approx_kernel, cudaFuncAttributeMaxDynamicSharedMemorySize, SMEM_TOTAL);

    prep_all_kernel<<<K / 8 + N / 8, 256>>>(E, Z);
    approx_kernel<<<(N / 128) * 2, 256, SMEM_TOTAL>>>(Z, E, zq, idxf, scal);
}

// round 17
// speedup vs baseline: 1.2986x; 1.2986x over previous
#include <cuda_runtime.h>
#include <cuda_fp16.h>
#include <cstdint>

#define D_DIM 256
#define NTOK  65536
#define KCODE 4096
#define NT_HALF 16    // tiles per CTA (half of E)

// ---------------- scratch globals ----------------
__device__ float  g_esqp[KCODE];        // esq + 2048 (fp32)
__device__ int    g_counts[KCODE];
__device__ float  g_partials[NTOK / 8];
__device__ __align__(16) __half g_Eh[KCODE * D_DIM];
__device__ __align__(16) __half g_Zh[NTOK * D_DIM];
__device__ __align__(16) uint32_t g_topk[NTOK * 8];
__device__ int    g_done;

// SMEM: A 64KB | B0 64KB | B1 64KB | tops 4KB
#define SM_A    0
#define SM_B0   65536
#define SM_B1   131072
#define SM_TOP  196608
#define SMEM_TOTAL 200704

static __device__ __forceinline__ uint32_t smem_u32(const void* p) {
    uint32_t a;
    asm("{ .reg .u64 t; cvta.to.shared.u64 t, %1; cvt.u32.u64 %0, t; }" : "=r"(a) : "l"(p));
    return a;
}
static __device__ __forceinline__ void ldsm4(uint32_t* r, uint32_t addr) {
    asm volatile("ldmatrix.sync.aligned.m8n8.x4.shared.b16 {%0,%1,%2,%3}, [%4];"
                 : "=r"(r[0]), "=r"(r[1]), "=r"(r[2]), "=r"(r[3]) : "r"(addr));
}
static __device__ __forceinline__ void hmma16816_f16(uint32_t& c0, uint32_t& c1,
                                                     const uint32_t* a, uint32_t b0, uint32_t b1) {
    asm volatile("mma.sync.aligned.m16n8k16.row.col.f16.f16.f16.f16 "
                 "{%0,%1}, {%2,%3,%4,%5}, {%6,%7}, {%0,%1};"
                 : "+r"(c0), "+r"(c1)
                 : "r"(a[0]), "r"(a[1]), "r"(a[2]), "r"(a[3]), "r"(b0), "r"(b1));
}
static __device__ __forceinline__ void cpasync16(uint32_t sa, const void* ga) {
    asm volatile("cp.async.cg.shared.global [%0], [%1], 16;" :: "r"(sa), "l"(ga));
}
static __device__ __forceinline__ void ins4u(uint32_t k, uint32_t& t0, uint32_t& t1,
                                             uint32_t& t2, uint32_t& t3) {
    if (k < t3) {
        uint32_t m2 = min(t2, k);  t3 = max(t2, k);
        uint32_t m1 = min(t1, m2); t2 = max(t1, m2);
        uint32_t m0 = min(t0, m1); t1 = max(t0, m1); t0 = m0;
    }
}

// ---------------- kernel 1: fused prep (E + Z) ----------------
__global__ void prep_all_kernel(const float* __restrict__ E, const float* __restrict__ Z) {
    int warp = threadIdx.x >> 5, lane = threadIdx.x & 31;
    if (blockIdx.x < KCODE / 8) {
        int k = blockIdx.x * 8 + warp;
        const float* row = E + (size_t)k * D_DIM;
        float4 a = *reinterpret_cast<const float4*>(row + lane * 8);
        float4 b = *reinterpret_cast<const float4*>(row + lane * 8 + 4);
        float s = a.x * a.x + a.y * a.y + a.z * a.z + a.w * a.w
                + b.x * b.x + b.y * b.y + b.z * b.z + b.w * b.w;
#pragma unroll
        for (int o = 16; o > 0; o >>= 1) s += __shfl_xor_sync(0xffffffffu, s, o);
        __half h[8];
        h[0] = __float2half_rn(a.x); h[1] = __float2half_rn(a.y);
        h[2] = __float2half_rn(a.z); h[3] = __float2half_rn(a.w);
        h[4] = __float2half_rn(b.x); h[5] = __float2half_rn(b.y);
        h[6] = __float2half_rn(b.z); h[7] = __float2half_rn(b.w);
        *reinterpret_cast<uint4*>(g_Eh + (size_t)k * D_DIM + lane * 8) = *reinterpret_cast<uint4*>(h);
        if (lane == 0) g_esqp[k] = s + 2048.0f;
        if (blockIdx.x < 16) g_counts[blockIdx.x * 256 + threadIdx.x] = 0;
    } else {
        int n = (blockIdx.x - KCODE / 8) * 8 + warp;
        const float* row = Z + (size_t)n * D_DIM;
        float4 a = *reinterpret_cast<const float4*>(row + lane * 8);
        float4 b = *reinterpret_cast<const float4*>(row + lane * 8 + 4);
        __half h[8];
        h[0] = __float2half_rn(a.x); h[1] = __float2half_rn(a.y);
        h[2] = __float2half_rn(a.z); h[3] = __float2half_rn(a.w);
        h[4] = __float2half_rn(b.x); h[5] = __float2half_rn(b.y);
        h[6] = __float2half_rn(b.z); h[7] = __float2half_rn(b.w);
        *reinterpret_cast<uint4*>(g_Zh + (size_t)n * D_DIM + lane * 8) = *reinterpret_cast<uint4*>(h);
    }
}

// ---------------- kernel 2: N-split HMMA GEMM + interleaved top-4 ----------------
static __device__ __forceinline__ void load_tile_f16(uint32_t dst, const __half* gsrc, int tid) {
    const char* gbase = (const char*)gsrc;
#pragma unroll
    for (int i = 0; i < 16; i++) {
        int c = tid + i * 256;
        int row = c >> 5, ch = c & 31;
        uint32_t sa = dst + row * 512 + (uint32_t)((ch ^ (row & 7)) << 4);
        cpasync16(sa, gbase + row * 512 + ch * 16);
    }
}

static __device__ __forceinline__ void tile_body(
    int nt, bool hasPrev, int n0base, uint32_t sb, int tid, int lane, int wm, int wn,
    uint32_t cur[2][8][2], uint32_t prev[2][8][2], uint32_t T[4][4])
{
    if (nt < NT_HALF - 1) asm volatile("cp.async.wait_group 1;" ::: "memory");
    else                  asm volatile("cp.async.wait_group 0;" ::: "memory");
    __syncthreads();
    const uint32_t Bb = sb + ((nt & 1) ? SM_B1 : SM_B0);

    float2 e2[8];
    const int kbase = n0base + (nt - 1) * 128 + wn * 64 + (lane & 3) * 2;
    if (hasPrev) {
#pragma unroll
        for (int nj = 0; nj < 8; nj++)
            e2[nj] = *reinterpret_cast<const float2*>(g_esqp + kbase + nj * 8);
    }

#pragma unroll
    for (int mi = 0; mi < 2; mi++)
#pragma unroll
        for (int nj = 0; nj < 8; nj++) { cur[mi][nj][0] = 0u; cur[mi][nj][1] = 0u; }

#pragma unroll
    for (int ks = 0; ks < 16; ks++) {
        uint32_t a[2][4], b[4][4];
#pragma unroll
        for (int mi = 0; mi < 2; mi++) {
            int ar = wm * 32 + mi * 16 + (lane & 15);
            int ch = ks * 2 + (lane >> 4);
            ldsm4(a[mi], sb + SM_A + ar * 512 + ((ch ^ (ar & 7)) << 4));
        }
#pragma unroll
        for (int g = 0; g < 4; g++) {
            int br = wn * 64 + g * 16 + (lane & 7) + ((lane >> 4) & 1) * 8;
            int ch = ks * 2 + ((lane >> 3) & 1);
            ldsm4(b[g], Bb + br * 512 + ((ch ^ (br & 7)) << 4));
        }
#pragma unroll
        for (int mi = 0; mi < 2; mi++)
#pragma unroll
            for (int g = 0; g < 4; g++) {
                hmma16816_f16(cur[mi][2 * g][0],     cur[mi][2 * g][1],     a[mi], b[g][0], b[g][1]);
                hmma16816_f16(cur[mi][2 * g + 1][0], cur[mi][2 * g + 1][1], a[mi], b[g][2], b[g][3]);
            }

        if (hasPrev) {
            const int nj = ks >> 1;
            const int mi = ks & 1;
            const int kb = kbase + nj * 8;
#pragma unroll
            for (int h = 0; h < 2; h++) {
                const int s = mi * 2 + h;
                float2 d = __half22float2(*reinterpret_cast<__half2*>(&prev[mi][nj][h]));
                float v0 = fmaf(-2.0f, d.x, e2[nj].x);
                float v1 = fmaf(-2.0f, d.y, e2[nj].y);
                uint32_t k0 = (__float_as_uint(v0) & 0xFFFFF000u) | (uint32_t)kb;
                uint32_t k1 = (__float_as_uint(v1) & 0xFFFFF000u) | (uint32_t)(kb + 1);
                ins4u(k0, T[s][0], T[s][1], T[s][2], T[s][3]);
                ins4u(k1, T[s][0], T[s][1], T[s][2], T[s][3]);
            }
        }
    }
    __syncthreads();
    if (nt + 2 < NT_HALF) {
        load_tile_f16(sb + ((nt & 1) ? SM_B1 : SM_B0),
                      g_Eh + (size_t)(n0base + (nt + 2) * 128) * D_DIM, tid);
        asm volatile("cp.async.commit_group;" ::: "memory");
    }
}

static __device__ __forceinline__ void tail_epilogue(
    int n0base, int lane, int wn, uint32_t prev[2][8][2], uint32_t T[4][4])
{
    const int kbase = n0base + (NT_HALF - 1) * 128 + wn * 64 + (lane & 3) * 2;
#pragma unroll
    for (int nj = 0; nj < 8; nj++) {
        const int kb = kbase + nj * 8;
        float2 e2 = *reinterpret_cast<const float2*>(g_esqp + kb);
#pragma unroll
        for (int mi = 0; mi < 2; mi++)
#pragma unroll
            for (int h = 0; h < 2; h++) {
                const int s = mi * 2 + h;
                float2 d = __half22float2(*reinterpret_cast<__half2*>(&prev[mi][nj][h]));
                float v0 = fmaf(-2.0f, d.x, e2.x);
                float v1 = fmaf(-2.0f, d.y, e2.y);
                uint32_t k0 = (__float_as_uint(v0) & 0xFFFFF000u) | (uint32_t)kb;
                uint32_t k1 = (__float_as_uint(v1) & 0xFFFFF000u) | (uint32_t)(kb + 1);
                ins4u(k0, T[s][0], T[s][1], T[s][2], T[s][3]);
                ins4u(k1, T[s][0], T[s][1], T[s][2], T[s][3]);
            }
    }
}

__global__ __launch_bounds__(256, 1)
void approx_kernel() {
    extern __shared__ char smem[];
    const uint32_t sb = smem_u32(smem);
    const int tid = threadIdx.x;
    const int lane = tid & 31;
    const int wid = tid >> 5;
    const int wm = wid & 3;
    const int wn = wid >> 2;
    const int m0 = (blockIdx.x >> 1) * 128;
    const int half = blockIdx.x & 1;
    const int n0base = half * (NT_HALF * 128);

    load_tile_f16(sb + SM_A, g_Zh + (size_t)m0 * D_DIM, tid);
    load_tile_f16(sb + SM_B0, g_Eh + (size_t)n0base * D_DIM, tid);
    asm volatile("cp.async.commit_group;" ::: "memory");
    load_tile_f16(sb + SM_B1, g_Eh + (size_t)(n0base + 128) * D_DIM, tid);
    asm volatile("cp.async.commit_group;" ::: "memory");

    uint32_t T[4][4];
#pragma unroll
    for (int s = 0; s < 4; s++) { T[s][0] = T[s][1] = T[s][2] = T[s][3] = 0xFFFFFFFFu; }

    uint32_t accA[2][8][2], accB[2][8][2];

#pragma unroll 1
    for (int p = 0; p < NT_HALF / 2; p++) {
        tile_body(2 * p,     (p > 0), n0base, sb, tid, lane, wm, wn, accA, accB, T);
        tile_body(2 * p + 1, true,    n0base, sb, tid, lane, wm, wn, accB, accA, T);
    }
    tail_epilogue(n0base, lane, wn, accB, T);

#pragma unroll
    for (int off = 1; off <= 2; off <<= 1) {
#pragma unroll
        for (int s = 0; s < 4; s++) {
            uint32_t o0 = __shfl_xor_sync(0xffffffffu, T[s][0], off);
            uint32_t o1 = __shfl_xor_sync(0xffffffffu, T[s][1], off);
            uint32_t o2 = __shfl_xor_sync(0xffffffffu, T[s][2], off);
            uint32_t o3 = __shfl_xor_sync(0xffffffffu, T[s][3], off);
            ins4u(o0, T[s][0], T[s][1], T[s][2], T[s][3]);
            ins4u(o1, T[s][0], T[s][1], T[s][2], T[s][3]);
            ins4u(o2, T[s][0], T[s][1], T[s][2], T[s][3]);
            ins4u(o3, T[s][0], T[s][1], T[s][2], T[s][3]);
        }
    }

    uint32_t* smk = reinterpret_cast<uint32_t*>(smem + SM_TOP);
    if ((lane & 3) == 0) {
#pragma unroll
        for (int s = 0; s < 4; s++) {
            int r = wm * 32 + (s >> 1) * 16 + (s & 1) * 8 + (lane >> 2);
            uint32_t* dst = smk + (r * 2 + wn) * 4;
            dst[0] = T[s][0]; dst[1] = T[s][1]; dst[2] = T[s][2]; dst[3] = T[s][3];
        }
    }
    __syncthreads();
    if (tid < 128) {
        uint4 A4 = *reinterpret_cast<uint4*>(smk + (tid * 2) * 4);
        uint4 B4 = *reinterpret_cast<uint4*>(smk + (tid * 2 + 1) * 4);
        uint32_t a0 = A4.x, a1 = A4.y, a2 = A4.z, a3 = A4.w;
        ins4u(B4.x, a0, a1, a2, a3);
        ins4u(B4.y, a0, a1, a2, a3);
        ins4u(B4.z, a0, a1, a2, a3);
        ins4u(B4.w, a0, a1, a2, a3);
        *reinterpret_cast<uint4*>(&g_topk[(size_t)(m0 + tid) * 8 + half * 4]) =
            make_uint4(a0, a1, a2, a3);
    }
}

// ---------------- kernel 3: merge halves + exact rescore + gather + loss + hist + finalize ----------------
__global__ void rescue_kernel(const float* __restrict__ Z, const float* __restrict__ E,
                              float* __restrict__ zq_out, float* __restrict__ out_idx_f,
                              float* __restrict__ out_scalars, int N, int K) {
    const int warp = threadIdx.x >> 5;
    const int lane = threadIdx.x & 31;
    const int token = blockIdx.x * 8 + warp;

    const float* zr = Z + (size_t)token * D_DIM;
    float4 z0 = *reinterpret_cast<const float4*>(zr + lane * 8);
    float4 z1 = *reinterpret_cast<const float4*>(zr + lane * 8 + 4);

    uint4 tkA = *reinterpret_cast<const uint4*>(&g_topk[(size_t)token * 8]);
    uint4 tkB = *reinterpret_cast<const uint4*>(&g_topk[(size_t)token * 8 + 4]);
    uint32_t a0 = tkA.x, a1 = tkA.y, a2 = tkA.z, a3 = tkA.w;
    ins4u(tkB.x, a0, a1, a2, a3);
    ins4u(tkB.y, a0, a1, a2, a3);
    ins4u(tkB.z, a0, a1, a2, a3);
    ins4u(tkB.w, a0, a1, a2, a3);

    int ks[4] = { (int)(a0 & 4095u), (int)(a1 & 4095u), (int)(a2 & 4095u), (int)(a3 & 4095u) };
    float dots[4];
#pragma unroll
    for (int j = 0; j < 4; j++) {
        const float* er = E + (size_t)ks[j] * D_DIM;
        float4 e0 = *reinterpret_cast<const float4*>(er + lane * 8);
        float4 e1 = *reinterpret_cast<const float4*>(er + lane * 8 + 4);
        dots[j] = z0.x * e0.x + z0.y * e0.y + z0.z * e0.z + z0.w * e0.w
                + z1.x * e1.x + z1.y * e1.y + z1.z * e1.z + z1.w * e1.w;
    }
#pragma unroll
    for (int o = 16; o > 0; o >>= 1)
#pragma unroll
        for (int j = 0; j < 4; j++) dots[j] += __shfl_xor_sync(0xffffffffu, dots[j], o);

    float bv = 3.4e38f; int bk = 0x7FFFFFFF;
#pragma unroll
    for (int j = 0; j < 4; j++) {
        float v = g_esqp[ks[j]] - 2048.0f - 2.0f * dots[j];
        if (v < bv || (v == bv && ks[j] < bk)) { bv = v; bk = ks[j]; }
    }

    const float* er = E + (size_t)bk * D_DIM;
    float* orow = zq_out + (size_t)token * D_DIM;
    float s = 0.f;
#pragma unroll
    for (int h = 0; h < 2; h++) {
        int off = h * 128 + lane * 4;
        float4 ev = *reinterpret_cast<const float4*>(er + off);
        float4 zv = *reinterpret_cast<const float4*>(zr + off);
        float dx = ev.x - zv.x, dy = ev.y - zv.y, dz = ev.z - zv.z, dw = ev.w - zv.w;
        s += dx * dx + dy * dy + dz * dz + dw * dw;
        *reinterpret_cast<float4*>(orow + off) = ev;
    }
    if (lane == 0) {
        atomicAdd(&g_counts[bk], 1);
        out_idx_f[token] = (float)bk;
    }
#pragma unroll
    for (int o = 16; o > 0; o >>= 1) s += __shfl_down_sync(0xffffffffu, s, o);
    __shared__ float sh[8];
    __shared__ int last;
    if (lane == 0) sh[warp] = s;
    __syncthreads();
    if (threadIdx.x == 0) {
        float t = 0.f;
        for (int w = 0; w < 8; w++) t += sh[w];
        g_partials[blockIdx.x] = t;
        __threadfence();
        int ticket = atomicAdd(&g_done, 1);
        last = (ticket == gridDim.x - 1) ? 1 : 0;
    }
    __syncthreads();
    if (!last) return;

    __shared__ float red[256];
    const int nPart = gridDim.x;
    float acc = 0.f;
    for (int i = threadIdx.x; i < nPart; i += 256) acc += g_partials[i];
    red[threadIdx.x] = acc;
    __syncthreads();
    for (int st = 128; st > 0; st >>= 1) {
        if (threadIdx.x < st) red[threadIdx.x] += red[threadIdx.x + st];
        __syncthreads();
    }
    float loss = 0.1f * red[0] / (float)((size_t)N * D_DIM);
    __syncthreads();
    float e = 0.f;
    for (int i = threadIdx.x; i < K; i += 256) {
        float p = (float)g_counts[i] / (float)N;
        e += p * logf(p + 1e-10f);
    }
    red[threadIdx.x] = e;
    __syncthreads();
    for (int st = 128; st > 0; st >>= 1) {
        if (threadIdx.x < st) red[threadIdx.x] += red[threadIdx.x + st];
        __syncthreads();
    }
    if (threadIdx.x == 0) {
        out_scalars[0] = loss;
        out_scalars[1] = expf(-red[0]);
        g_done = 0;
    }
}

extern "C" void kernel_launch(void* const* d_in, const int* in_sizes, int n_in,
                              void* d_out, int out_size) {
    const float* Z = (const float*)d_in[0];
    const float* E = (const float*)d_in[1];
    int N = in_sizes[0] / D_DIM;
    int K = in_sizes[1] / D_DIM;

    float* out  = (float*)d_out;
    float* zq   = out;
    float* idxf = out + (size_t)N * D_DIM;
    float* scal = idxf + N;

    cudaFuncSetAttribute(approx_kernel, cudaFuncAttributeMaxDynamicSharedMemorySize, SMEM_TOTAL);

    prep_all_kernel<<<K / 8 + N / 8, 256>>>(E, Z);
    approx_kernel<<<(N / 128) * 2, 256, SMEM_TOTAL>>>();
    rescue_kernel<<<N / 8, 256>>>(Z, E, zq, idxf, scal, N, K);
}